// round 3
// baseline (speedup 1.0000x reference)
#include <cuda_runtime.h>
#include <cstdint>

#define IMG 128
#define BR  512
#define NSTROKES 1024
#define LSTROKES 256

// Scratch (device-global; no mallocs allowed).
__device__ uint32_t g_mask[2 * (BR * BR / 32)];     // fine mask: 16384 words (fallback only)
__device__ uint32_t g_coarse[512];                  // 1 bit per fine word == all-ones
__device__ float    g_sp[NSTROKES * 16];            // per-stroke warp 2x3, color, brush idx

// ---------------------------------------------------------------------------
// Kernel 1 (fused): blocks [0,64) build fine mask + coarse summary;
// blocks [64,96) compute stroke warp matrices (fp64 sin/cos over 32 SMs).
// ---------------------------------------------------------------------------
__global__ void prep_and_mask_kernel(const float* __restrict__ params,
                                     const float* __restrict__ brushes) {
    const int bid = blockIdx.x;
    const int t = threadIdx.x;

    if (bid < 64) {
        const int word = bid * 256 + t;                 // 0 .. 16383
        const float4* src = (const float4*)brushes + word * 8;
        uint32_t m = 0;
        #pragma unroll
        for (int j = 0; j < 8; ++j) {
            float4 v = src[j];
            m |= ((v.x > 0.0f) ? 1u : 0u) << (4 * j + 0);
            m |= ((v.y > 0.0f) ? 1u : 0u) << (4 * j + 1);
            m |= ((v.z > 0.0f) ? 1u : 0u) << (4 * j + 2);
            m |= ((v.w > 0.0f) ? 1u : 0u) << (4 * j + 3);
        }
        g_mask[word] = m;
        // coarse: warp covers 32 consecutive words -> one coarse word
        unsigned full = __ballot_sync(0xFFFFFFFFu, m == 0xFFFFFFFFu);
        if ((t & 31) == 0) g_coarse[word >> 5] = full;
    } else {
        if (t >= 32) return;
        const int n = (bid - 64) * 32 + t;              // 0 .. 1023
        const float* p = params + n * 8;
        float x0 = p[0], y0 = p[1], w = p[2], h = p[3], th = p[4];

        // JAX: sin(fl32(pi) * theta), f32 product; correctly-rounded double
        // sin/cos keeps binary-alpha decisions bit-stable vs reference.
        float prod = 3.14159274101257324219f * th;
        float s = (float)sin((double)prod);
        float c = (float)cos((double)prod);

        float tx = 1.0f - 2.0f * x0;
        float ty = 1.0f - 2.0f * y0;
        float w00 = c / w;
        float w01 = s / w;
        float w02 = (tx * c) / w + (ty * s) / w;
        float w10 = -(s / h);
        float w11 = c / h;
        float w12 = (ty * c) / h - (tx * s) / h;

        float* o = g_sp + n * 16;
        o[0] = w00; o[1] = w01; o[2] = w02;
        o[3] = w10; o[4] = w11; o[5] = w12;
        o[6] = p[5]; o[7] = p[6]; o[8] = p[7];
        o[9] = (h > w) ? 0.0f : 1.0f;
        o[10] = o[11] = o[12] = o[13] = o[14] = o[15] = 0.0f;
    }
}

// ---------------------------------------------------------------------------
// Render. 128 threads = 16x8 pixel tile. Backward stroke scan, 64-stroke
// staged param buffer, coarse-mask alpha test with rare global fallback.
// ---------------------------------------------------------------------------
struct SMem {
    uint32_t coarse[512];   // 2 KB: both brushes
    float    sp[64 * 16];   // 4 KB: current 64-stroke stage
    int      more;
};

__device__ __forceinline__ bool alpha_at(const uint32_t* __restrict__ s_coarse,
                                         int brush, float gx, float gy) {
    float x = ((gx + 1.0f) * 512.0f - 1.0f) * 0.5f;
    float y = ((gy + 1.0f) * 512.0f - 1.0f) * 0.5f;
    int ix = __float2int_rn(x);
    int iy = __float2int_rn(y);
    if ((unsigned)ix >= 512u || (unsigned)iy >= 512u) return false;
    int wi = (brush << 13) + (iy << 4) + (ix >> 5);        // fine word index
    if ((s_coarse[wi >> 5] >> (wi & 31)) & 1u) return true; // word all-ones
    return (__ldg(g_mask + wi) >> (ix & 31)) & 1u;          // rare fallback
}

__device__ __forceinline__ float tap(const float* __restrict__ im, int ix, int iy) {
    bool valid = ((unsigned)ix < 512u) && ((unsigned)iy < 512u);
    int cx = min(max(ix, 0), 511);
    int cy = min(max(iy, 0), 511);
    float v = __ldg(im + cy * 512 + cx);
    return valid ? v : 0.0f;
}

__global__ __launch_bounds__(128)
void render_kernel(const float* __restrict__ brushes, float* __restrict__ out) {
    __shared__ SMem sm;
    const int b = blockIdx.z;
    const int t = threadIdx.x;

    // Stage coarse mask (2 KB): 1 uint4 per thread.
    ((uint4*)sm.coarse)[t] = ((const uint4*)g_coarse)[t];

    const int tx = t & 15, ty = t >> 4;
    const int w = blockIdx.x * 16 + tx;
    const int h = blockIdx.y * 8 + ty;
    const float bx = (2.0f * (float)w + 1.0f) * (1.0f / 128.0f) - 1.0f;
    const float by = (2.0f * (float)h + 1.0f) * (1.0f / 128.0f) - 1.0f;

    float oR = 0.0f, oG = 0.0f, oB = 0.0f;
    bool done = false;

    #pragma unroll 1
    for (int stage = 0; stage < 4; ++stage) {
        const int hi = 255 - 64 * stage;
        const int lo = hi - 63;
        if (t == 0) sm.more = 0;
        // Stage 64 strokes (4 KB): 2 float4 per thread.
        {
            const float4* gp = (const float4*)(g_sp + ((size_t)b * LSTROKES + lo) * 16);
            float4* sp4 = (float4*)sm.sp;
            sp4[t]       = gp[t];
            sp4[t + 128] = gp[t + 128];
        }
        __syncthreads();

        if (!__all_sync(0xFFFFFFFFu, done)) {
            #pragma unroll 1
            for (int l = hi; l >= lo; --l) {
                if (__all_sync(0xFFFFFFFFu, done)) break;
                if (!done) {
                    const float* sp = sm.sp + (l - lo) * 16;
                    const float w00 = sp[0], w01 = sp[1], w02 = sp[2];
                    const float w10 = sp[3], w11 = sp[4], w12 = sp[5];
                    const int   idx = (sp[9] != 0.0f) ? 1 : 0;

                    float gx = fmaf(bx, w00, fmaf(by, w01, w02));
                    float gy = fmaf(bx, w10, fmaf(by, w11, w12));

                    if (alpha_at(sm.coarse, idx, gx, gy)) {
                        bool ok = true;
                        #pragma unroll
                        for (int k = 0; k < 9; ++k) {
                            const int dh = k / 3 - 1, dw = k % 3 - 1;
                            if (dh == 0 && dw == 0) continue;
                            if ((unsigned)(h + dh) >= 128u) continue;
                            if ((unsigned)(w + dw) >= 128u) continue;
                            const float bxn = bx + (float)dw * 0.015625f;
                            const float byn = by + (float)dh * 0.015625f;
                            const float gxn = fmaf(bxn, w00, fmaf(byn, w01, w02));
                            const float gyn = fmaf(bxn, w10, fmaf(byn, w11, w12));
                            ok &= alpha_at(sm.coarse, idx, gxn, gyn);
                        }
                        if (ok) {
                            const float* im = brushes + (size_t)idx * (BR * BR);
                            const float x = ((gx + 1.0f) * 512.0f - 1.0f) * 0.5f;
                            const float y = ((gy + 1.0f) * 512.0f - 1.0f) * 0.5f;
                            const float xf = floorf(x), yf = floorf(y);
                            const int x0i = (int)xf, y0i = (int)yf;
                            const float wx1 = x - xf, wx0 = 1.0f - wx1;
                            const float wy1 = y - yf, wy0 = 1.0f - wy1;
                            const float sV =
                                tap(im, x0i,     y0i)     * (wx0 * wy0) +
                                tap(im, x0i + 1, y0i)     * (wx1 * wy0) +
                                tap(im, x0i,     y0i + 1) * (wx0 * wy1) +
                                tap(im, x0i + 1, y0i + 1) * (wx1 * wy1);
                            oR = sV * sp[6];
                            oG = sV * sp[7];
                            oB = sV * sp[8];
                            done = true;
                        }
                    }
                }
            }
        }

        if (!done) sm.more = 1;
        __syncthreads();
        if (!sm.more) break;
    }

    const int base = ((b * 3) * IMG + h) * IMG + w;
    out[base]                 = oR;
    out[base + IMG * IMG]     = oG;
    out[base + 2 * IMG * IMG] = oB;
}

// ---------------------------------------------------------------------------
extern "C" void kernel_launch(void* const* d_in, const int* in_sizes, int n_in,
                              void* d_out, int out_size) {
    const float* params  = (const float*)d_in[0];   // (4,256,8)
    const float* brushes = (const float*)d_in[1];   // (2,1,512,512)
    float* out = (float*)d_out;                     // (4,3,128,128)

    (void)in_sizes; (void)n_in; (void)out_size;

    prep_and_mask_kernel<<<96, 256>>>(params, brushes);

    dim3 grid(IMG / 16, IMG / 8, 4);                 // 512 blocks x 128 threads
    render_kernel<<<grid, 128>>>(brushes, out);
}

// round 4
// speedup vs baseline: 1.2369x; 1.2369x over previous
#include <cuda_runtime.h>
#include <cstdint>

#define IMG 128
#define BR  512
#define NSTROKES 1024
#define LSTROKES 256

// Scratch (device-global; no mallocs allowed).
__device__ uint32_t g_mask[2 * (BR * BR / 32)];   // fine brush>0 mask (fallback only)
__device__ uint32_t g_coarse[512];                // 1 bit per fine word == all-ones
// SoA stroke params
__device__ float g_w00[NSTROKES], g_w01[NSTROKES], g_w02[NSTROKES];
__device__ float g_w10[NSTROKES], g_w11[NSTROKES], g_w12[NSTROKES];
__device__ float g_cr[NSTROKES], g_cg[NSTROKES], g_cb[NSTROKES];
__device__ int   g_bidx[NSTROKES];

// ---------------------------------------------------------------------------
// Kernel 1 (fused): blocks [0,64) build fine mask + coarse summary;
// blocks [64,96) compute stroke warp matrices (fp64 sin/cos over 32 SMs).
// ---------------------------------------------------------------------------
__global__ void prep_and_mask_kernel(const float* __restrict__ params,
                                     const float* __restrict__ brushes) {
    const int bid = blockIdx.x;
    const int t = threadIdx.x;

    if (bid < 64) {
        const int word = bid * 256 + t;                 // 0 .. 16383
        const float4* src = (const float4*)brushes + word * 8;
        uint32_t m = 0;
        #pragma unroll
        for (int j = 0; j < 8; ++j) {
            float4 v = src[j];
            m |= ((v.x > 0.0f) ? 1u : 0u) << (4 * j + 0);
            m |= ((v.y > 0.0f) ? 1u : 0u) << (4 * j + 1);
            m |= ((v.z > 0.0f) ? 1u : 0u) << (4 * j + 2);
            m |= ((v.w > 0.0f) ? 1u : 0u) << (4 * j + 3);
        }
        g_mask[word] = m;
        unsigned full = __ballot_sync(0xFFFFFFFFu, m == 0xFFFFFFFFu);
        if ((t & 31) == 0) g_coarse[word >> 5] = full;
    } else {
        if (t >= 32) return;
        const int n = (bid - 64) * 32 + t;              // 0 .. 1023
        const float* p = params + n * 8;
        float x0 = p[0], y0 = p[1], w = p[2], h = p[3], th = p[4];

        // JAX: sin(fl32(pi)*theta), f32 product; correctly-rounded double
        // sin/cos keeps binary-alpha decisions bit-stable vs reference.
        float prod = 3.14159274101257324219f * th;
        float s = (float)sin((double)prod);
        float c = (float)cos((double)prod);

        float tx = 1.0f - 2.0f * x0;
        float ty = 1.0f - 2.0f * y0;
        g_w00[n] = c / w;
        g_w01[n] = s / w;
        g_w02[n] = (tx * c) / w + (ty * s) / w;
        g_w10[n] = -(s / h);
        g_w11[n] = c / h;
        g_w12[n] = (ty * c) / h - (tx * s) / h;
        g_cr[n] = p[5]; g_cg[n] = p[6]; g_cb[n] = p[7];
        g_bidx[n] = (h > w) ? 0 : 1;
    }
}

// ---------------------------------------------------------------------------
// Render: warp = 8x4 pixel tile. Lane-parallel stroke/tile interval reject
// (32 strokes per round), then serial per-pixel processing of candidates.
// ---------------------------------------------------------------------------
struct SMem {
    uint32_t coarse[512];                       // 2 KB
    float w00[256], w01[256], w02[256];
    float w10[256], w11[256], w12[256];
    float cr[256], cg[256], cb[256];
    int   bidx[256];
};

__device__ __forceinline__ bool alpha_at(const uint32_t* __restrict__ s_coarse,
                                         int brush, float gx, float gy) {
    float x = ((gx + 1.0f) * 512.0f - 1.0f) * 0.5f;
    float y = ((gy + 1.0f) * 512.0f - 1.0f) * 0.5f;
    int ix = __float2int_rn(x);
    int iy = __float2int_rn(y);
    if ((unsigned)ix >= 512u || (unsigned)iy >= 512u) return false;
    int wi = (brush << 13) + (iy << 4) + (ix >> 5);
    if ((s_coarse[wi >> 5] >> (wi & 31)) & 1u) return true;
    return (__ldg(g_mask + wi) >> (ix & 31)) & 1u;
}

__device__ __forceinline__ float tap(const float* __restrict__ im, int ix, int iy) {
    bool valid = ((unsigned)ix < 512u) && ((unsigned)iy < 512u);
    int cx = min(max(ix, 0), 511);
    int cy = min(max(iy, 0), 511);
    float v = __ldg(im + cy * 512 + cx);
    return valid ? v : 0.0f;
}

__global__ __launch_bounds__(128)
void render_kernel(const float* __restrict__ brushes, float* __restrict__ out) {
    __shared__ SMem sm;
    const int b = blockIdx.z;
    const int t = threadIdx.x;

    // Stage coarse mask (2 KB) + batch stroke params SoA (10 KB).
    ((uint4*)sm.coarse)[t] = ((const uint4*)g_coarse)[t];
    {
        const int off = b * LSTROKES;
        #pragma unroll
        for (int i = 0; i < 2; ++i) {
            int s = t + i * 128;
            sm.w00[s] = g_w00[off + s]; sm.w01[s] = g_w01[off + s];
            sm.w02[s] = g_w02[off + s]; sm.w10[s] = g_w10[off + s];
            sm.w11[s] = g_w11[off + s]; sm.w12[s] = g_w12[off + s];
            sm.cr[s]  = g_cr[off + s];  sm.cg[s]  = g_cg[off + s];
            sm.cb[s]  = g_cb[off + s];  sm.bidx[s] = g_bidx[off + s];
        }
    }
    __syncthreads();

    const int warp = t >> 5, lane = t & 31;
    // Block covers 16x8 pixels; each warp an 8x4 sub-tile.
    const int tileX = blockIdx.x * 16 + (warp & 1) * 8;
    const int tileY = blockIdx.y * 8 + (warp >> 1) * 4;
    const int w = tileX + (lane & 7);
    const int h = tileY + (lane >> 3);
    const float bx = (2.0f * (float)w + 1.0f) * (1.0f / 128.0f) - 1.0f;
    const float by = (2.0f * (float)h + 1.0f) * (1.0f / 128.0f) - 1.0f;
    // Tile corner coords (exact powers of two).
    const float bx0 = (2.0f * (float)tileX + 1.0f) * (1.0f / 128.0f) - 1.0f;
    const float bx1 = bx0 + 14.0f * (1.0f / 128.0f);
    const float by0 = (2.0f * (float)tileY + 1.0f) * (1.0f / 128.0f) - 1.0f;
    const float by1 = by0 + 6.0f * (1.0f / 128.0f);

    float oR = 0.0f, oG = 0.0f, oB = 0.0f;
    bool done = false;
    bool allDone = false;

    #pragma unroll 1
    for (int base = LSTROKES - 32; base >= 0 && !allDone; base -= 32) {
        // Lane-parallel tile/stroke interval overlap test (32 strokes at once).
        const int sl = base + lane;
        const float a  = sm.w00[sl], bb = sm.w01[sl], cc = sm.w02[sl];
        const float d  = sm.w10[sl], e  = sm.w11[sl], f  = sm.w12[sl];
        const float gxlo = cc + fminf(bx0 * a, bx1 * a) + fminf(by0 * bb, by1 * bb);
        const float gxhi = cc + fmaxf(bx0 * a, bx1 * a) + fmaxf(by0 * bb, by1 * bb);
        const float gylo = f  + fminf(bx0 * d, bx1 * d) + fminf(by0 * e, by1 * e);
        const float gyhi = f  + fmaxf(bx0 * d, bx1 * d) + fmaxf(by0 * e, by1 * e);
        const bool cand = (gxhi >= -1.002f) & (gxlo <= 1.002f) &
                          (gyhi >= -1.002f) & (gylo <= 1.002f);
        unsigned m = __ballot_sync(0xFFFFFFFFu, cand);

        while (m) {
            const int bit = 31 - __clz(m);        // highest stroke first
            m &= ~(1u << bit);
            const int l = base + bit;

            const float w00 = sm.w00[l], w01 = sm.w01[l], w02 = sm.w02[l];
            const float w10 = sm.w10[l], w11 = sm.w11[l], w12 = sm.w12[l];
            const int   idx = sm.bidx[l];

            if (!done) {
                float gx = fmaf(bx, w00, fmaf(by, w01, w02));
                float gy = fmaf(bx, w10, fmaf(by, w11, w12));
                if (alpha_at(sm.coarse, idx, gx, gy)) {
                    bool ok = true;
                    #pragma unroll
                    for (int k = 0; k < 9; ++k) {
                        const int dh = k / 3 - 1, dw = k % 3 - 1;
                        if (dh == 0 && dw == 0) continue;
                        if ((unsigned)(h + dh) >= 128u) continue;
                        if ((unsigned)(w + dw) >= 128u) continue;
                        const float bxn = bx + (float)dw * 0.015625f;
                        const float byn = by + (float)dh * 0.015625f;
                        const float gxn = fmaf(bxn, w00, fmaf(byn, w01, w02));
                        const float gyn = fmaf(bxn, w10, fmaf(byn, w11, w12));
                        ok &= alpha_at(sm.coarse, idx, gxn, gyn);
                    }
                    if (ok) {
                        const float* im = brushes + (size_t)idx * (BR * BR);
                        const float x = ((gx + 1.0f) * 512.0f - 1.0f) * 0.5f;
                        const float y = ((gy + 1.0f) * 512.0f - 1.0f) * 0.5f;
                        const float xf = floorf(x), yf = floorf(y);
                        const int x0i = (int)xf, y0i = (int)yf;
                        const float wx1 = x - xf, wx0 = 1.0f - wx1;
                        const float wy1 = y - yf, wy0 = 1.0f - wy1;
                        const float sV =
                            tap(im, x0i,     y0i)     * (wx0 * wy0) +
                            tap(im, x0i + 1, y0i)     * (wx1 * wy0) +
                            tap(im, x0i,     y0i + 1) * (wx0 * wy1) +
                            tap(im, x0i + 1, y0i + 1) * (wx1 * wy1);
                        oR = sV * sm.cr[l];
                        oG = sV * sm.cg[l];
                        oB = sV * sm.cb[l];
                        done = true;
                    }
                }
            }
            if (__all_sync(0xFFFFFFFFu, done)) { allDone = true; break; }
        }
    }

    const int outb = ((b * 3) * IMG + h) * IMG + w;
    out[outb]                 = oR;
    out[outb + IMG * IMG]     = oG;
    out[outb + 2 * IMG * IMG] = oB;
}

// ---------------------------------------------------------------------------
extern "C" void kernel_launch(void* const* d_in, const int* in_sizes, int n_in,
                              void* d_out, int out_size) {
    const float* params  = (const float*)d_in[0];   // (4,256,8)
    const float* brushes = (const float*)d_in[1];   // (2,1,512,512)
    float* out = (float*)d_out;                     // (4,3,128,128)

    (void)in_sizes; (void)n_in; (void)out_size;

    prep_and_mask_kernel<<<96, 256>>>(params, brushes);

    dim3 grid(IMG / 16, IMG / 8, 4);                // 512 blocks x 128 threads
    render_kernel<<<grid, 128>>>(brushes, out);
}

// round 5
// speedup vs baseline: 1.2557x; 1.0152x over previous
#include <cuda_runtime.h>
#include <cstdint>

#define IMG 128
#define BR  512
#define NSTROKES 1024
#define LSTROKES 256

// Scratch (device-global; no mallocs allowed).
__device__ uint32_t g_mask[2 * (BR * BR / 32)];   // fine brush>0 mask (fallback)
__device__ uint32_t g_coarse[512];                // 1 bit per fine word == all-ones
// SoA stroke params
__device__ float g_w00[NSTROKES], g_w01[NSTROKES], g_w02[NSTROKES];
__device__ float g_w10[NSTROKES], g_w11[NSTROKES], g_w12[NSTROKES];
__device__ float g_cr[NSTROKES], g_cg[NSTROKES], g_cb[NSTROKES];
__device__ int   g_bidx[NSTROKES];

// ---------------------------------------------------------------------------
// Kernel 1 (fused): blocks [0,64) build fine mask + coarse summary;
// blocks [64,96) compute stroke warp matrices (fp64 sin/cos over 32 SMs).
// ---------------------------------------------------------------------------
__global__ void prep_and_mask_kernel(const float* __restrict__ params,
                                     const float* __restrict__ brushes) {
    const int bid = blockIdx.x;
    const int t = threadIdx.x;

    if (bid < 64) {
        const int word = bid * 256 + t;                 // 0 .. 16383
        const float4* src = (const float4*)brushes + word * 8;
        uint32_t m = 0;
        #pragma unroll
        for (int j = 0; j < 8; ++j) {
            float4 v = src[j];
            m |= ((v.x > 0.0f) ? 1u : 0u) << (4 * j + 0);
            m |= ((v.y > 0.0f) ? 1u : 0u) << (4 * j + 1);
            m |= ((v.z > 0.0f) ? 1u : 0u) << (4 * j + 2);
            m |= ((v.w > 0.0f) ? 1u : 0u) << (4 * j + 3);
        }
        g_mask[word] = m;
        unsigned full = __ballot_sync(0xFFFFFFFFu, m == 0xFFFFFFFFu);
        if ((t & 31) == 0) g_coarse[word >> 5] = full;
    } else {
        if (t >= 32) return;
        const int n = (bid - 64) * 32 + t;              // 0 .. 1023
        const float* p = params + n * 8;
        float x0 = p[0], y0 = p[1], w = p[2], h = p[3], th = p[4];

        // JAX: sin(fl32(pi)*theta), f32 product; correctly-rounded double
        // sin/cos keeps binary-alpha decisions bit-stable vs reference.
        float prod = 3.14159274101257324219f * th;
        float s = (float)sin((double)prod);
        float c = (float)cos((double)prod);

        float tx = 1.0f - 2.0f * x0;
        float ty = 1.0f - 2.0f * y0;
        g_w00[n] = c / w;
        g_w01[n] = s / w;
        g_w02[n] = (tx * c) / w + (ty * s) / w;
        g_w10[n] = -(s / h);
        g_w11[n] = c / h;
        g_w12[n] = (ty * c) / h - (tx * s) / h;
        g_cr[n] = p[5]; g_cg[n] = p[6]; g_cb[n] = p[7];
        g_bidx[n] = (h > w) ? 0 : 1;
    }
}

// ---------------------------------------------------------------------------
// Render: block = 128 threads = 4 warps, all covering ONE 8x4 pixel tile.
// Warp k scans its disjoint 64-stroke chunk (top-down, early exit); per-pixel
// winners combined by max (winner == max stroke index with eroded alpha).
// ---------------------------------------------------------------------------
__device__ __forceinline__ bool alpha_slow(int brush, float gx, float gy) {
    float x = ((gx + 1.0f) * 512.0f - 1.0f) * 0.5f;
    float y = ((gy + 1.0f) * 512.0f - 1.0f) * 0.5f;
    int ix = __float2int_rn(x);
    int iy = __float2int_rn(y);
    if ((unsigned)ix >= 512u || (unsigned)iy >= 512u) return false;
    int wi = (brush << 13) + (iy << 4) + (ix >> 5);
    if ((__ldg(g_coarse + (wi >> 5)) >> (wi & 31)) & 1u) return true;
    return (__ldg(g_mask + wi) >> (ix & 31)) & 1u;
}

__device__ __forceinline__ bool alpha_fast(float gx, float gy) {
    // all-ones mask: alpha == in-bounds of rounded sample coords
    float x = ((gx + 1.0f) * 512.0f - 1.0f) * 0.5f;
    float y = ((gy + 1.0f) * 512.0f - 1.0f) * 0.5f;
    int ix = __float2int_rn(x);
    int iy = __float2int_rn(y);
    return ((unsigned)ix < 512u) & ((unsigned)iy < 512u);
}

__device__ __forceinline__ float tap(const float* __restrict__ im, int ix, int iy) {
    bool valid = ((unsigned)ix < 512u) && ((unsigned)iy < 512u);
    int cx = min(max(ix, 0), 511);
    int cy = min(max(iy, 0), 511);
    float v = __ldg(im + cy * 512 + cx);
    return valid ? v : 0.0f;
}

__global__ __launch_bounds__(128)
void render_kernel(const float* __restrict__ brushes, float* __restrict__ out) {
    __shared__ int s_win[4][32];

    const int t = threadIdx.x;
    const int warp = t >> 5, lane = t & 31;
    const int b = blockIdx.z;
    const int off = b * LSTROKES;

    // Block-uniform "every brush texel > 0" flag (common case: true).
    bool fullv = true;
    #pragma unroll
    for (int i = 0; i < 4; ++i) fullv &= (__ldg(g_coarse + t + 128 * i) == 0xFFFFFFFFu);
    const bool allones = __syncthreads_and(fullv ? 1 : 0) != 0;

    const int tileX = blockIdx.x * 8;
    const int tileY = blockIdx.y * 4;
    const int w = tileX + (lane & 7);
    const int h = tileY + (lane >> 3);
    const float bx = (2.0f * (float)w + 1.0f) * (1.0f / 128.0f) - 1.0f;
    const float by = (2.0f * (float)h + 1.0f) * (1.0f / 128.0f) - 1.0f;
    const float bx0 = (2.0f * (float)tileX + 1.0f) * (1.0f / 128.0f) - 1.0f;
    const float bx1 = bx0 + 14.0f * (1.0f / 128.0f);
    const float by0 = (2.0f * (float)tileY + 1.0f) * (1.0f / 128.0f) - 1.0f;
    const float by1 = by0 + 6.0f * (1.0f / 128.0f);

    int myWin = -1;
    bool done = false;

    const int hi = 255 - 64 * warp;                 // chunk: [hi-63, hi]
    #pragma unroll 1
    for (int r = 0; r < 2; ++r) {
        const int base = hi - 31 - 32 * r;          // strokes [base, base+31]
        // Lane-parallel tile/stroke interval overlap test.
        const int sl = off + base + lane;
        const float a  = __ldg(g_w00 + sl), bb = __ldg(g_w01 + sl), cc = __ldg(g_w02 + sl);
        const float d  = __ldg(g_w10 + sl), e  = __ldg(g_w11 + sl), f  = __ldg(g_w12 + sl);
        const float gxlo = cc + fminf(bx0 * a, bx1 * a) + fminf(by0 * bb, by1 * bb);
        const float gxhi = cc + fmaxf(bx0 * a, bx1 * a) + fmaxf(by0 * bb, by1 * bb);
        const float gylo = f  + fminf(bx0 * d, bx1 * d) + fminf(by0 * e, by1 * e);
        const float gyhi = f  + fmaxf(bx0 * d, bx1 * d) + fmaxf(by0 * e, by1 * e);
        const bool cand = (gxhi >= -1.002f) & (gxlo <= 1.002f) &
                          (gyhi >= -1.002f) & (gylo <= 1.002f);
        unsigned m = __ballot_sync(0xFFFFFFFFu, cand);

        while (m) {
            const int bit = 31 - __clz(m);          // highest stroke first
            m &= ~(1u << bit);
            const int l = base + bit;
            const int gl = off + l;

            if (!done) {
                const float w00 = __ldg(g_w00 + gl), w01 = __ldg(g_w01 + gl), w02 = __ldg(g_w02 + gl);
                const float w10 = __ldg(g_w10 + gl), w11 = __ldg(g_w11 + gl), w12 = __ldg(g_w12 + gl);
                const int   idx = __ldg(g_bidx + gl);

                const float gx = fmaf(bx, w00, fmaf(by, w01, w02));
                const float gy = fmaf(bx, w10, fmaf(by, w11, w12));
                const bool center = allones ? alpha_fast(gx, gy)
                                            : alpha_slow(idx, gx, gy);
                if (center) {
                    bool ok = true;
                    #pragma unroll
                    for (int k = 0; k < 9; ++k) {
                        const int dh = k / 3 - 1, dw = k % 3 - 1;
                        if (dh == 0 && dw == 0) continue;
                        if ((unsigned)(h + dh) >= 128u) continue;
                        if ((unsigned)(w + dw) >= 128u) continue;
                        const float bxn = bx + (float)dw * 0.015625f;
                        const float byn = by + (float)dh * 0.015625f;
                        const float gxn = fmaf(bxn, w00, fmaf(byn, w01, w02));
                        const float gyn = fmaf(bxn, w10, fmaf(byn, w11, w12));
                        ok &= allones ? alpha_fast(gxn, gyn)
                                      : alpha_slow(idx, gxn, gyn);
                    }
                    if (ok) { myWin = l; done = true; }
                }
            }
            if (__all_sync(0xFFFFFFFFu, done)) break;
        }
        if (__all_sync(0xFFFFFFFFu, done)) break;
    }

    s_win[warp][lane] = myWin;
    __syncthreads();

    // Warp 0: combine winners, bilinear-sample, write.
    if (warp == 0) {
        const int wn = max(max(s_win[0][lane], s_win[1][lane]),
                           max(s_win[2][lane], s_win[3][lane]));
        float oR = 0.0f, oG = 0.0f, oB = 0.0f;
        if (wn >= 0) {
            const int gl = off + wn;
            const float w00 = __ldg(g_w00 + gl), w01 = __ldg(g_w01 + gl), w02 = __ldg(g_w02 + gl);
            const float w10 = __ldg(g_w10 + gl), w11 = __ldg(g_w11 + gl), w12 = __ldg(g_w12 + gl);
            const int   idx = __ldg(g_bidx + gl);
            const float gx = fmaf(bx, w00, fmaf(by, w01, w02));
            const float gy = fmaf(bx, w10, fmaf(by, w11, w12));
            const float* im = brushes + (size_t)idx * (BR * BR);
            const float x = ((gx + 1.0f) * 512.0f - 1.0f) * 0.5f;
            const float y = ((gy + 1.0f) * 512.0f - 1.0f) * 0.5f;
            const float xf = floorf(x), yf = floorf(y);
            const int x0i = (int)xf, y0i = (int)yf;
            const float wx1 = x - xf, wx0 = 1.0f - wx1;
            const float wy1 = y - yf, wy0 = 1.0f - wy1;
            const float sV =
                tap(im, x0i,     y0i)     * (wx0 * wy0) +
                tap(im, x0i + 1, y0i)     * (wx1 * wy0) +
                tap(im, x0i,     y0i + 1) * (wx0 * wy1) +
                tap(im, x0i + 1, y0i + 1) * (wx1 * wy1);
            oR = sV * __ldg(g_cr + gl);
            oG = sV * __ldg(g_cg + gl);
            oB = sV * __ldg(g_cb + gl);
        }
        const int outb = ((b * 3) * IMG + h) * IMG + w;
        out[outb]                 = oR;
        out[outb + IMG * IMG]     = oG;
        out[outb + 2 * IMG * IMG] = oB;
    }
}

// ---------------------------------------------------------------------------
extern "C" void kernel_launch(void* const* d_in, const int* in_sizes, int n_in,
                              void* d_out, int out_size) {
    const float* params  = (const float*)d_in[0];   // (4,256,8)
    const float* brushes = (const float*)d_in[1];   // (2,1,512,512)
    float* out = (float*)d_out;                     // (4,3,128,128)

    (void)in_sizes; (void)n_in; (void)out_size;

    prep_and_mask_kernel<<<96, 256>>>(params, brushes);

    dim3 grid(IMG / 8, IMG / 4, 4);                 // 2048 blocks x 128 threads
    render_kernel<<<grid, 128>>>(brushes, out);
}

// round 6
// speedup vs baseline: 1.6452x; 1.3102x over previous
#include <cuda_runtime.h>
#include <cstdint>

#define IMG 128
#define BR  512
#define NSTROKES 1024
#define LSTROKES 256

// Scratch (device-global; no mallocs allowed).
__device__ uint32_t g_mask[2 * (BR * BR / 32)];   // fine brush>0 mask (fallback)
__device__ uint32_t g_coarse[512];                // 1 bit per fine word == all-ones
// SoA stroke params
__device__ float g_w00[NSTROKES], g_w01[NSTROKES], g_w02[NSTROKES];
__device__ float g_w10[NSTROKES], g_w11[NSTROKES], g_w12[NSTROKES];
__device__ float g_cr[NSTROKES], g_cg[NSTROKES], g_cb[NSTROKES];
__device__ int   g_bidx[NSTROKES];

// ---------------------------------------------------------------------------
// Kernel 1 (fused): blocks [0,64) build fine mask + coarse summary;
// blocks [64,96) compute stroke warp matrices (fp64 sin/cos over 32 SMs).
// ---------------------------------------------------------------------------
__global__ void prep_and_mask_kernel(const float* __restrict__ params,
                                     const float* __restrict__ brushes) {
    const int bid = blockIdx.x;
    const int t = threadIdx.x;

    if (bid < 64) {
        const int word = bid * 256 + t;                 // 0 .. 16383
        const float4* src = (const float4*)brushes + word * 8;
        uint32_t m = 0;
        #pragma unroll
        for (int j = 0; j < 8; ++j) {
            float4 v = src[j];
            m |= ((v.x > 0.0f) ? 1u : 0u) << (4 * j + 0);
            m |= ((v.y > 0.0f) ? 1u : 0u) << (4 * j + 1);
            m |= ((v.z > 0.0f) ? 1u : 0u) << (4 * j + 2);
            m |= ((v.w > 0.0f) ? 1u : 0u) << (4 * j + 3);
        }
        g_mask[word] = m;
        unsigned full = __ballot_sync(0xFFFFFFFFu, m == 0xFFFFFFFFu);
        if ((t & 31) == 0) g_coarse[word >> 5] = full;
    } else {
        if (t >= 32) return;
        const int n = (bid - 64) * 32 + t;              // 0 .. 1023
        const float* p = params + n * 8;
        float x0 = p[0], y0 = p[1], w = p[2], h = p[3], th = p[4];

        // JAX: sin(fl32(pi)*theta), f32 product; correctly-rounded double
        // sin/cos keeps binary-alpha decisions bit-stable vs reference.
        float prod = 3.14159274101257324219f * th;
        float s = (float)sin((double)prod);
        float c = (float)cos((double)prod);

        float tx = 1.0f - 2.0f * x0;
        float ty = 1.0f - 2.0f * y0;
        g_w00[n] = c / w;
        g_w01[n] = s / w;
        g_w02[n] = (tx * c) / w + (ty * s) / w;
        g_w10[n] = -(s / h);
        g_w11[n] = c / h;
        g_w12[n] = (ty * c) / h - (tx * s) / h;
        g_cr[n] = p[5]; g_cg[n] = p[6]; g_cb[n] = p[7];
        g_bidx[n] = (h > w) ? 0 : 1;
    }
}

// ---------------------------------------------------------------------------
// Render helpers
// ---------------------------------------------------------------------------
__device__ __forceinline__ bool alpha_slow(int brush, float gx, float gy) {
    float x = ((gx + 1.0f) * 512.0f - 1.0f) * 0.5f;
    float y = ((gy + 1.0f) * 512.0f - 1.0f) * 0.5f;
    int ix = __float2int_rn(x);
    int iy = __float2int_rn(y);
    if ((unsigned)ix >= 512u || (unsigned)iy >= 512u) return false;
    int wi = (brush << 13) + (iy << 4) + (ix >> 5);
    if ((__ldg(g_coarse + (wi >> 5)) >> (wi & 31)) & 1u) return true;
    return (__ldg(g_mask + wi) >> (ix & 31)) & 1u;
}

__device__ __forceinline__ bool valid_fast(float bxn, float byn,
                                           float w00, float w01, float w02,
                                           float w10, float w11, float w12) {
    // all-ones mask: eroded alpha point test == rounded sample in-bounds.
    const float gx = fmaf(bxn, w00, fmaf(byn, w01, w02));
    const float gy = fmaf(bxn, w10, fmaf(byn, w11, w12));
    const float x = ((gx + 1.0f) * 512.0f - 1.0f) * 0.5f;
    const float y = ((gy + 1.0f) * 512.0f - 1.0f) * 0.5f;
    const int ix = __float2int_rn(x);
    const int iy = __float2int_rn(y);
    return ((unsigned)ix < 512u) & ((unsigned)iy < 512u);
}

__device__ __forceinline__ float tap(const float* __restrict__ im, int ix, int iy) {
    bool valid = ((unsigned)ix < 512u) && ((unsigned)iy < 512u);
    int cx = min(max(ix, 0), 511);
    int cy = min(max(iy, 0), 511);
    float v = __ldg(im + cy * 512 + cx);
    return valid ? v : 0.0f;
}

__device__ __forceinline__ float bgrid(int i) {     // exact base-grid coord
    return (2.0f * (float)i + 1.0f) * (1.0f / 128.0f) - 1.0f;
}

// ---------------------------------------------------------------------------
// Render: block = 4 warps over ONE 8x4 tile. Warp k scans strokes
// l ≡ k (mod 4) DESCENDING (per-deck early exit); winner = max over decks.
// Candidate accept: tile-wide 4-corner test (O(1)) else per-pixel 4-corner.
// ---------------------------------------------------------------------------
__global__ __launch_bounds__(128)
void render_kernel(const float* __restrict__ brushes, float* __restrict__ out) {
    __shared__ int s_win[4][32];

    const int t = threadIdx.x;
    const int warp = t >> 5, lane = t & 31;
    const int b = blockIdx.z;
    const int off = b * LSTROKES;

    // Block-uniform "every brush texel > 0" flag (common case: true).
    bool fullv = true;
    #pragma unroll
    for (int i = 0; i < 4; ++i) fullv &= (__ldg(g_coarse + t + 128 * i) == 0xFFFFFFFFu);
    const bool allones = __syncthreads_and(fullv ? 1 : 0) != 0;

    const int tileX = blockIdx.x * 8;
    const int tileY = blockIdx.y * 4;
    const int w = tileX + (lane & 7);
    const int h = tileY + (lane >> 3);
    const float bx = bgrid(w);
    const float by = bgrid(h);
    // Per-pixel clipped stencil corner coords (exact: multiples of 2^-7).
    const float c64 = 0.015625f;                      // 1/64 grid step
    const float bxl = bx - ((w > 0)   ? c64 : 0.0f);
    const float bxh = bx + ((w < 127) ? c64 : 0.0f);
    const float byl = by - ((h > 0)   ? c64 : 0.0f);
    const float byh = by + ((h < 127) ? c64 : 0.0f);
    // Tile-wide expanded-stencil rect corners.
    const float tx0 = bgrid(max(tileX - 1, 0)), tx1 = bgrid(min(tileX + 8, 127));
    const float ty0 = bgrid(max(tileY - 1, 0)), ty1 = bgrid(min(tileY + 4, 127));
    // Interval-test tile extent.
    const float ix0 = bgrid(tileX), ix1 = bgrid(tileX + 7);
    const float iy0 = bgrid(tileY), iy1 = bgrid(tileY + 3);

    int myWin = -1;
    bool done = false;

    #pragma unroll 1
    for (int r = 0; r < 2 && !__all_sync(0xFFFFFFFFu, done); ++r) {
        // Deck position p = r*32+lane -> stroke l = (63-p)*4 + warp (descending).
        const int p = r * 32 + lane;
        const int sl = off + (63 - p) * 4 + warp;
        const float a  = __ldg(g_w00 + sl), bb = __ldg(g_w01 + sl), cc = __ldg(g_w02 + sl);
        const float d  = __ldg(g_w10 + sl), e  = __ldg(g_w11 + sl), f  = __ldg(g_w12 + sl);
        const float gxlo = cc + fminf(ix0 * a, ix1 * a) + fminf(iy0 * bb, iy1 * bb);
        const float gxhi = cc + fmaxf(ix0 * a, ix1 * a) + fmaxf(iy0 * bb, iy1 * bb);
        const float gylo = f  + fminf(ix0 * d, ix1 * d) + fminf(iy0 * e, iy1 * e);
        const float gyhi = f  + fmaxf(ix0 * d, ix1 * d) + fmaxf(iy0 * e, iy1 * e);
        const bool cand = (gxhi >= -1.002f) & (gxlo <= 1.002f) &
                          (gyhi >= -1.002f) & (gylo <= 1.002f);
        unsigned m = __ballot_sync(0xFFFFFFFFu, cand);

        while (m) {
            const int bit = __ffs(m) - 1;             // lowest lane = highest stroke
            m &= m - 1;
            const int l = (63 - (r * 32 + bit)) * 4 + warp;
            const int gl = off + l;

            const float w00 = __ldg(g_w00 + gl), w01 = __ldg(g_w01 + gl), w02 = __ldg(g_w02 + gl);
            const float w10 = __ldg(g_w10 + gl), w11 = __ldg(g_w11 + gl), w12 = __ldg(g_w12 + gl);

            if (allones) {
                // Tile-wide O(1) accept: 4 corners of expanded stencil rect.
                const bool tOK =
                    valid_fast(tx0, ty0, w00, w01, w02, w10, w11, w12) &
                    valid_fast(tx0, ty1, w00, w01, w02, w10, w11, w12) &
                    valid_fast(tx1, ty0, w00, w01, w02, w10, w11, w12) &
                    valid_fast(tx1, ty1, w00, w01, w02, w10, w11, w12);
                if (tOK) {
                    if (!done) { myWin = l; done = true; }
                } else if (!done) {
                    // Per-pixel exact 4-corner test (monotone => corners suffice).
                    const bool ok =
                        valid_fast(bxl, byl, w00, w01, w02, w10, w11, w12) &
                        valid_fast(bxl, byh, w00, w01, w02, w10, w11, w12) &
                        valid_fast(bxh, byl, w00, w01, w02, w10, w11, w12) &
                        valid_fast(bxh, byh, w00, w01, w02, w10, w11, w12);
                    if (ok) { myWin = l; done = true; }
                }
            } else if (!done) {
                const int idx = __ldg(g_bidx + gl);
                const float gx = fmaf(bx, w00, fmaf(by, w01, w02));
                const float gy = fmaf(bx, w10, fmaf(by, w11, w12));
                if (alpha_slow(idx, gx, gy)) {
                    bool ok = true;
                    #pragma unroll
                    for (int k = 0; k < 9; ++k) {
                        const int dh = k / 3 - 1, dw = k % 3 - 1;
                        if (dh == 0 && dw == 0) continue;
                        if ((unsigned)(h + dh) >= 128u) continue;
                        if ((unsigned)(w + dw) >= 128u) continue;
                        const float bxn = bx + (float)dw * c64;
                        const float byn = by + (float)dh * c64;
                        const float gxn = fmaf(bxn, w00, fmaf(byn, w01, w02));
                        const float gyn = fmaf(bxn, w10, fmaf(byn, w11, w12));
                        ok &= alpha_slow(idx, gxn, gyn);
                    }
                    if (ok) { myWin = l; done = true; }
                }
            }
            if (__all_sync(0xFFFFFFFFu, done)) break;
        }
    }

    s_win[warp][lane] = myWin;
    __syncthreads();

    // Warp 0: combine deck winners by max, bilinear-sample, write.
    if (warp == 0) {
        const int wn = max(max(s_win[0][lane], s_win[1][lane]),
                           max(s_win[2][lane], s_win[3][lane]));
        float oR = 0.0f, oG = 0.0f, oB = 0.0f;
        if (wn >= 0) {
            const int gl = off + wn;
            const float w00 = __ldg(g_w00 + gl), w01 = __ldg(g_w01 + gl), w02 = __ldg(g_w02 + gl);
            const float w10 = __ldg(g_w10 + gl), w11 = __ldg(g_w11 + gl), w12 = __ldg(g_w12 + gl);
            const int   idx = __ldg(g_bidx + gl);
            const float gx = fmaf(bx, w00, fmaf(by, w01, w02));
            const float gy = fmaf(bx, w10, fmaf(by, w11, w12));
            const float* im = brushes + (size_t)idx * (BR * BR);
            const float x = ((gx + 1.0f) * 512.0f - 1.0f) * 0.5f;
            const float y = ((gy + 1.0f) * 512.0f - 1.0f) * 0.5f;
            const float xf = floorf(x), yf = floorf(y);
            const int x0i = (int)xf, y0i = (int)yf;
            const float wx1 = x - xf, wx0 = 1.0f - wx1;
            const float wy1 = y - yf, wy0 = 1.0f - wy1;
            const float sV =
                tap(im, x0i,     y0i)     * (wx0 * wy0) +
                tap(im, x0i + 1, y0i)     * (wx1 * wy0) +
                tap(im, x0i,     y0i + 1) * (wx0 * wy1) +
                tap(im, x0i + 1, y0i + 1) * (wx1 * wy1);
            oR = sV * __ldg(g_cr + gl);
            oG = sV * __ldg(g_cg + gl);
            oB = sV * __ldg(g_cb + gl);
        }
        const int outb = ((b * 3) * IMG + h) * IMG + w;
        out[outb]                 = oR;
        out[outb + IMG * IMG]     = oG;
        out[outb + 2 * IMG * IMG] = oB;
    }
}

// ---------------------------------------------------------------------------
extern "C" void kernel_launch(void* const* d_in, const int* in_sizes, int n_in,
                              void* d_out, int out_size) {
    const float* params  = (const float*)d_in[0];   // (4,256,8)
    const float* brushes = (const float*)d_in[1];   // (2,1,512,512)
    float* out = (float*)d_out;                     // (4,3,128,128)

    (void)in_sizes; (void)n_in; (void)out_size;

    prep_and_mask_kernel<<<96, 256>>>(params, brushes);

    dim3 grid(IMG / 8, IMG / 4, 4);                 // 2048 blocks x 128 threads
    render_kernel<<<grid, 128>>>(brushes, out);
}